// round 17
// baseline (speedup 1.0000x reference)
#include <cuda_runtime.h>
#include <cstdint>

// AdditiveAttention: out[b,q,v] = softmax_k( sum_h w_v[h]*tanh(q~[b,q,h]+k~[b,k,h]) ) @ V
// B=4, Q=256, K=1024, IN=256, H=128, V=256.

typedef unsigned long long ull;

// Scratch (__device__ globals — no allocation allowed)
__device__ float g_qp[4 * 256 * 128];         // projected queries
__device__ float g_kp[4 * 1024 * 128];        // projected keys
__device__ float g_pacc[32 * 256 * 256];      // partial acc [b*8+kq][q][v]
__device__ float g_psum[32 * 256];            // partial exp-sums [b*8+kq][q]
__device__ unsigned int g_cnt[64];            // per-(b,qt16) counters (self-reset)

__device__ __forceinline__ float tanh_apx(float x) {
    float y;
    asm("tanh.approx.f32 %0, %1;" : "=f"(y) : "f"(x));
    return y;
}

__device__ __forceinline__ void fma2(ull& d, ull a, ull b) {
    asm("fma.rn.f32x2 %0, %1, %2, %0;" : "+l"(d) : "l"(a), "l"(b));
}

__device__ __forceinline__ ull pack2(float x) {
    ull r;
    asm("mov.b64 %0, {%1, %1};" : "=l"(r) : "f"(x));
    return r;
}

__device__ __forceinline__ void ldgsts16(uint32_t saddr, const void* g) {
    asm volatile("cp.async.cg.shared.global [%0], [%1], 16;"
                 :: "r"(saddr), "l"(g));
}
__device__ __forceinline__ void cp_commit() {
    asm volatile("cp.async.commit_group;" ::: "memory");
}
__device__ __forceinline__ void cp_wait0() {
    asm volatile("cp.async.wait_group 0;" ::: "memory");
}

// ---------------------------------------------------------------------------
// K_proj: projections straight from raw W. 320 blocks x 256 threads,
// 16 rows each: [0,256) keys -> g_kp, [256,320) queries -> g_qp.
// Grid 320 => ~2.2 blocks/SM (4+ warps/SMSP) vs prior 160 (2/SMSP) — the
// R16 profile showed k_proj latency-starved at 1 block/SM.
// Per 32-i tile: thread (wh = t>>1, whalf = t&1) LDGs W[wh][...16] and
// STS-transposes into wt[buf][i][wh]; double-buffered, LDG issued before
// compute. X staged transposed as float2 row-pairs xs2[i*9+p] (8 pairs).
// Inner per i: 1 LDS.64 w + 2 pack + 2 LDS.64 x + 4 fma2 -> 8 FMAs.
// SMEM 50.2KB.
// ---------------------------------------------------------------------------
#define SMEM_PROJ (18432 + 32768)   // xs2 [256][9]f2 + wt [2][32*128]f

__global__ __launch_bounds__(256, 4) void k_proj(
    const float* __restrict__ queries, const float* __restrict__ keys,
    const float* __restrict__ Wq, const float* __restrict__ Wk) {
    extern __shared__ float psm[];
    float2* xs2 = (float2*)psm;          // [256][9] float2
    float*  wt  = psm + 4608;            // [2][32*128] floats

    int bid = blockIdx.x;
    int t = threadIdx.x;

    const float* src;
    const float* W;
    float* dst;
    int r0g;
    if (bid < 256) { src = keys;    W = Wk; dst = g_kp; r0g = bid * 16; }
    else           { src = queries; W = Wq; dst = g_qp; r0g = (bid - 256) * 16; }

    int wh = t >> 1;                 // 0..127 (W output-feature row)
    int whalf = t & 1;               // i-subrange half
    const float4* wrow = (const float4*)(W + wh * 256 + whalf * 16);

    // ---- load W tile 0 into regs ----
    float4 wr0 = wrow[0], wr1 = wrow[1], wr2 = wrow[2], wr3 = wrow[3];

    // ---- stage X (16 rows x 256 i) transposed into row-pair float2 ----
    const float4* s4 = (const float4*)(src + r0g * 256);
    float* xsf = (float*)xs2;
    #pragma unroll 4
    for (int n = 0; n < 4; ++n) {
        int idx4 = t + n * 256;                       // 0..1023 float4
        int r = idx4 >> 6, i4 = idx4 & 63;            // r 0..15
        float4 v = s4[idx4];
        xsf[(i4 * 4 + 0) * 18 + r] = v.x;
        xsf[(i4 * 4 + 1) * 18 + r] = v.y;
        xsf[(i4 * 4 + 2) * 18 + r] = v.z;
        xsf[(i4 * 4 + 3) * 18 + r] = v.w;
    }

    // ---- STS tile 0 transposed: wt[0][i][wh] ----
    {
        float wv[16];
        *(float4*)&wv[0] = wr0; *(float4*)&wv[4] = wr1;
        *(float4*)&wv[8] = wr2; *(float4*)&wv[12] = wr3;
        #pragma unroll
        for (int j = 0; j < 16; ++j)
            wt[(whalf * 16 + j) * 128 + wh] = wv[j];
    }
    __syncthreads();

    int h2 = (t & 63) * 2;
    int rh = t >> 6;                     // 0..3 -> row-pairs rh*2, rh*2+1
    const float2* xp = xs2 + rh * 2;
    ull acc[2][2] = {{0ull,0ull},{0ull,0ull}};

    for (int tau = 0; tau < 8; ++tau) {
        float4 nr0, nr1, nr2, nr3;
        if (tau + 1 < 8) {
            const float4* nsrc = wrow + (tau + 1) * 8;  // +32 floats
            nr0 = nsrc[0]; nr1 = nsrc[1]; nr2 = nsrc[2]; nr3 = nsrc[3];
        }

        const float* wb = wt + (tau & 1) * 4096;
        #pragma unroll 8
        for (int ii = 0; ii < 32; ++ii) {
            float2 w2 = *(const float2*)&wb[ii * 128 + h2];
            ull wa = pack2(w2.x);
            ull wbp = pack2(w2.y);
            const float2* xi = xp + (tau * 32 + ii) * 9;
            ull x0 = *(const ull*)&xi[0];
            ull x1 = *(const ull*)&xi[1];
            fma2(acc[0][0], x0, wa); fma2(acc[0][1], x0, wbp);
            fma2(acc[1][0], x1, wa); fma2(acc[1][1], x1, wbp);
        }

        if (tau + 1 < 8) {
            float wv[16];
            *(float4*)&wv[0] = nr0; *(float4*)&wv[4] = nr1;
            *(float4*)&wv[8] = nr2; *(float4*)&wv[12] = nr3;
            float* wn = wt + ((tau + 1) & 1) * 4096;
            #pragma unroll
            for (int j = 0; j < 16; ++j)
                wn[(whalf * 16 + j) * 128 + wh] = wv[j];
            __syncthreads();
        }
    }

    // write 4 rows x 2 h per thread as coalesced float2 (over h)
    #pragma unroll
    for (int p = 0; p < 2; ++p) {
        float2 A = *(float2*)&acc[p][0];   // h2   : {row even, row odd}
        float2 Bv = *(float2*)&acc[p][1];  // h2+1 : {row even, row odd}
        int r = r0g + (rh * 2 + p) * 2;
        float2 o0 = make_float2(A.x, Bv.x);
        float2 o1 = make_float2(A.y, Bv.y);
        *(float2*)&dst[r * 128 + h2] = o0;
        *(float2*)&dst[(r + 1) * 128 + h2] = o1;
    }
}

// ---------------------------------------------------------------------------
// K_attn9: UNCHANGED from R16 (measured 45.2us, near masked-MUFU floor).
// 512 blocks x 512 threads: b = bid&3, kq = (bid>>2)&7, qt = bid>>5.
// ---------------------------------------------------------------------------
#define SMEM_ATTN (65536 + 8192 + 512 + 16384 + 128)

__global__ __launch_bounds__(512) void k_attn9(
    const float* __restrict__ values, const int* __restrict__ valid_lens,
    const float* __restrict__ w_v, float* __restrict__ out) {
    extern __shared__ float sm[];
    float4* ks4  = (float4*)sm;                      // [2][2048] float4 64KB
    float*  qs   = sm + 16384;                       // [16][128]        8KB
    float*  wvs  = qs + 2048;                        // [128]
    float2* eb2  = (float2*)(wvs + 128);             // [2][16*64] {e,e} 16KB
    float*  wsum = (float*)(eb2 + 2048);             // [16][2]
    __shared__ unsigned int s_old;

    int bid = blockIdx.x;
    int b = bid & 3;
    int kq = (bid >> 2) & 7;
    int qt = bid >> 5;                // 0..15
    int vlen = valid_lens[b];
    int k0 = kq * 128;
    if (k0 >= vlen) return;
    int nch = min(2, (vlen - k0 + 63) >> 6);

    int t = threadIdx.x;
    int q0 = qt * 16;
    int ka = t & 63;                  // A: key within chunk
    int qg = (t >> 6) & 7;            // warp-uniform q-group (0..7), 2 q each
    int vp = (t & 63) * 4;            // C: 4 v-cols, coalesced

    const float4* kp4 = (const float4*)(g_kp + (b * 1024 + k0) * 128);
    const float* Vb = values + (b * 1024 + k0) * 256;
    uint32_t ksaddr = (uint32_t)__cvta_generic_to_shared(ks4);

    // ---- issue chunk 0 copy (64 k x 32 float4 = 2048) ----
    #pragma unroll
    for (int n = 0; n < 4; ++n) {
        int idx = t + n * 512;
        int kk = idx >> 5, h4 = idx & 31;
        uint32_t d = ksaddr + (uint32_t)((kk * 32 + ((h4 + kk) & 31)) * 16);
        ldgsts16(d, kp4 + kk * 32 + h4);
    }
    cp_commit();

    // ---- load qs (16 rows), wvs while copy flies ----
    for (int i = t; i < 2048; i += 512)
        qs[i] = g_qp[(b * 256 + q0) * 128 + i];
    if (t < 128) wvs[t] = w_v[t];
    cp_wait0();

    ull acc[2][2] = {{0ull,0ull},{0ull,0ull}};
    float lsum[2] = {0.f, 0.f};
    const float* qbase = qs + qg * 2 * 128;

    for (int c = 0; c < nch; ++c) {
        __syncthreads();   // chunk c + qs visible; eb(c-1) visible

        if (c + 1 < nch) {
            const float4* srcc = kp4 + 2048;
            #pragma unroll
            for (int n = 0; n < 4; ++n) {
                int idx = t + n * 512;
                int kk = idx >> 5, h4 = idx & 31;
                uint32_t d = ksaddr +
                    (uint32_t)((2048 + kk * 32 + ((h4 + kk) & 31)) * 16);
                ldgsts16(d, srcc + kk * 32 + h4);
            }
            cp_commit();
        }

        const float4* ksb = ks4 + (c & 1) * 2048 + ka * 32;
        float s0 = 0.f, s1 = 0.f;        // 2 q chains

        if (c == 0) {
            #pragma unroll 4
            for (int j = 0; j < 32; ++j) {
                float4 kv = ksb[(j + ka) & 31];
                float4 w4 = *(const float4*)&wvs[j * 4];
                float4 qa0 = *(const float4*)&qbase[j * 4];
                float4 qa1 = *(const float4*)&qbase[128 + j * 4];
                s0 = fmaf(w4.x, tanh_apx(qa0.x + kv.x), s0);
                s0 = fmaf(w4.y, tanh_apx(qa0.y + kv.y), s0);
                s0 = fmaf(w4.z, tanh_apx(qa0.z + kv.z), s0);
                s0 = fmaf(w4.w, tanh_apx(qa0.w + kv.w), s0);
                s1 = fmaf(w4.x, tanh_apx(qa1.x + kv.x), s1);
                s1 = fmaf(w4.y, tanh_apx(qa1.y + kv.y), s1);
                s1 = fmaf(w4.z, tanh_apx(qa1.z + kv.z), s1);
                s1 = fmaf(w4.w, tanh_apx(qa1.w + kv.w), s1);
            }
        } else {
            const float2* eb = eb2 + ((c & 1) ^ 1) * 1024 + qg * 2 * 64;
            const float* Vp = Vb + (c - 1) * 64 * 256 + vp;
            #pragma unroll 2
            for (int j = 0; j < 32; ++j) {
                float4 kv = ksb[(j + ka) & 31];
                float4 w4 = *(const float4*)&wvs[j * 4];
                float4 qa0 = *(const float4*)&qbase[j * 4];
                float4 qa1 = *(const float4*)&qbase[128 + j * 4];
                s0 = fmaf(w4.x, tanh_apx(qa0.x + kv.x), s0);
                s0 = fmaf(w4.y, tanh_apx(qa0.y + kv.y), s0);
                s0 = fmaf(w4.z, tanh_apx(qa0.z + kv.z), s0);
                s0 = fmaf(w4.w, tanh_apx(qa0.w + kv.w), s0);
                s1 = fmaf(w4.x, tanh_apx(qa1.x + kv.x), s1);
                s1 = fmaf(w4.y, tanh_apx(qa1.y + kv.y), s1);
                s1 = fmaf(w4.z, tanh_apx(qa1.z + kv.z), s1);
                s1 = fmaf(w4.w, tanh_apx(qa1.w + kv.w), s1);
                // Phase C of previous chunk: k = 2j, 2j+1
                #pragma unroll
                for (int dk = 0; dk < 2; ++dk) {
                    int kk = 2 * j + dk;
                    float4 v0 = *(const float4*)&Vp[kk * 256];
                    ull v01 = *(ull*)&v0.x, v23 = *(ull*)&v0.z;
                    float2 e0 = eb[kk];
                    float2 e1 = eb[64 + kk];
                    fma2(acc[0][0], *(ull*)&e0, v01);
                    fma2(acc[0][1], *(ull*)&e0, v23);
                    fma2(acc[1][0], *(ull*)&e1, v01);
                    fma2(acc[1][1], *(ull*)&e1, v23);
                }
            }
        }

        // exp + store e (duplicated) for 2 q, masked
        int kg = k0 + c * 64 + ka;
        bool valid = (kg < vlen);
        float e0 = valid ? __expf(s0) : 0.f;
        float e1 = valid ? __expf(s1) : 0.f;
        float2* ebw = eb2 + (c & 1) * 1024 + qg * 2 * 64 + ka;
        ebw[0]  = make_float2(e0, e0);
        ebw[64] = make_float2(e1, e1);
        lsum[0] += e0; lsum[1] += e1;
        if (c + 1 < nch) cp_wait0();
    }

    // ---- epilogue: C(nch-1) ----
    __syncthreads();
    {
        const float2* eb = eb2 + ((nch - 1) & 1) * 1024 + qg * 2 * 64;
        const float* Vp = Vb + (nch - 1) * 64 * 256 + vp;
        #pragma unroll 4
        for (int kk = 0; kk < 64; ++kk) {
            float4 v0 = *(const float4*)&Vp[kk * 256];
            ull v01 = *(ull*)&v0.x, v23 = *(ull*)&v0.z;
            float2 e0 = eb[kk];
            float2 e1 = eb[64 + kk];
            fma2(acc[0][0], *(ull*)&e0, v01);
            fma2(acc[0][1], *(ull*)&e0, v23);
            fma2(acc[1][0], *(ull*)&e1, v01);
            fma2(acc[1][1], *(ull*)&e1, v23);
        }
    }

    // per-q exp sums
    #pragma unroll
    for (int qi = 0; qi < 2; ++qi) {
        float v = lsum[qi];
        v += __shfl_xor_sync(0xffffffffu, v, 16);
        v += __shfl_xor_sync(0xffffffffu, v, 8);
        v += __shfl_xor_sync(0xffffffffu, v, 4);
        v += __shfl_xor_sync(0xffffffffu, v, 2);
        v += __shfl_xor_sync(0xffffffffu, v, 1);
        lsum[qi] = v;
    }
    int lane = t & 31, w = t >> 5;    // 16 warps
    if (lane == 0) {
        wsum[w * 2 + 0] = lsum[0];
        wsum[w * 2 + 1] = lsum[1];
    }
    __syncthreads();
    if (t < 16) {
        int g = t >> 1, qi = t & 1;
        g_psum[(b * 8 + kq) * 256 + q0 + g * 2 + qi] =
            wsum[(2 * g) * 2 + qi] + wsum[(2 * g + 1) * 2 + qi];
    }

    // partial acc write: 2 q rows x 4 v per thread
    #pragma unroll
    for (int qi = 0; qi < 2; ++qi) {
        float* pa = &g_pacc[(((b * 8 + kq) * 256) + q0 + qg * 2 + qi) * 256 + vp];
        float4 o;
        o.x = ((float2*)&acc[qi][0])->x; o.y = ((float2*)&acc[qi][0])->y;
        o.z = ((float2*)&acc[qi][1])->x; o.w = ((float2*)&acc[qi][1])->y;
        *(float4*)pa = o;
    }

    // ---- combine-on-last-arrival per (b, qt) ----
    __threadfence();
    __syncthreads();
    if (t == 0) s_old = atomicAdd(&g_cnt[b * 16 + qt], 1u);
    __syncthreads();

    int np = (vlen + 127) >> 7;           // participants 1..8
    if (s_old == (unsigned)(np - 1)) {
        __threadfence();                  // acquire: peers' partials visible
        int v = t & 255;
        int qh = t >> 8;                  // 0/1 -> q rows qh*8 .. qh*8+7
        for (int qi = 0; qi < 8; ++qi) {
            int qq = q0 + qh * 8 + qi;
            float a = 0.f, ssum = 0.f;
            for (int p = 0; p < np; ++p) {
                a += g_pacc[((b * 8 + p) * 256 + qq) * 256 + v];
                ssum += g_psum[(b * 8 + p) * 256 + qq];
            }
            out[(b * 256 + qq) * 256 + v] = a / ssum;
        }
        if (t == 0) atomicExch(&g_cnt[b * 16 + qt], 0u);
    }
}

// ---------------------------------------------------------------------------
extern "C" void kernel_launch(void* const* d_in, const int* in_sizes, int n_in,
                              void* d_out, int out_size) {
    const float* queries    = (const float*)d_in[0];  // [4,256,256]
    const float* keys       = (const float*)d_in[1];  // [4,1024,256]
    const float* values     = (const float*)d_in[2];  // [4,1024,256]
    const int*   valid_lens = (const int*)d_in[3];    // [4]
    const float* W_q        = (const float*)d_in[4];  // [128,256]
    const float* W_k        = (const float*)d_in[5];  // [128,256]
    const float* w_v        = (const float*)d_in[6];  // [128]
    float* out = (float*)d_out;                       // [4,256,256]

    cudaFuncSetAttribute(k_proj, cudaFuncAttributeMaxDynamicSharedMemorySize,
                         SMEM_PROJ);
    cudaFuncSetAttribute(k_attn9, cudaFuncAttributeMaxDynamicSharedMemorySize,
                         SMEM_ATTN);

    k_proj<<<320, 256, SMEM_PROJ>>>(queries, keys, W_q, W_k);
    k_attn9<<<512, 512, SMEM_ATTN>>>(values, valid_lens, w_v, out);
}